// round 7
// baseline (speedup 1.0000x reference)
#include <cuda_runtime.h>
#include <math.h>

// ---------------- problem constants ----------------
#define T_STEPS 16384
#define HDIM    1028
#define G4      4112          // 4*HDIM
#define KPAD    1032          // HDIM padded to multiple of 8 for GEMM
#define NCTA    129           // persistent CTAs: 129*8 = 1032 >= 1028 units
#define UPER    8             // hidden units per CTA (32 gate rows, 1 per lane)
#define NW      20            // warps per CTA
#define NT      640           // threads per CTA
#define CPW     52            // h-columns per warp: 20*52 = 1040 >= 1028
#define HB      1040          // staged h length (padded)
#define RREP    4             // h broadcast replicas (spread L2 slices)
#define RSTRIDE 1056          // floats between replicas (4224 B)

// ---------------- device scratch (static: no allocation allowed) ----------------
__device__ __align__(16) float g_h1[(long long)T_STEPS * KPAD];   // layer-0 outputs, K-padded
__device__ __align__(16) float g_ihc[(long long)T_STEPS * G4];    // w_ih1 @ h1  (precomputed)
__device__ __align__(16) float g_h2[(long long)T_STEPS * HDIM];   // layer-1 outputs
__device__ __align__(16) float g_hrep[2][RREP * RSTRIDE];         // DOUBLE-BUFFERED replicated h
__device__ __align__(16) float g_wpad[(long long)G4 * KPAD];      // padded w_ih1
__device__ unsigned g_ready[NCTA];                                // per-CTA step flags

// ---------------- pad w_ih1 to KPAD stride ----------------
__global__ void pad_w_kernel(const float* __restrict__ w) {
    int n = blockIdx.x;
    for (int k = threadIdx.x; k < KPAD; k += blockDim.x)
        g_wpad[(long long)n * KPAD + k] = (k < HDIM) ? w[(long long)n * HDIM + k] : 0.f;
}

// accurate activations (fast-math __expf drifts to ~4e-3 over 16384 recurrent
// steps -- measured in R5; library expf/tanhf give 3e-7 and only run on 8 lanes)
__device__ __forceinline__ float sigm(float x) { return 1.f / (1.f + expf(-x)); }

// ---------------- persistent LSTM recurrence ----------------
// 129 CTAs, 1/SM. CTA s owns units [s*8, s*8+8) -> 32 gate rows, one per lane:
// lane l -> gate g = l>>3, unit uu = l&7, global row = g*HDIM + s*8 + uu.
// Warp w owns h-columns [w*52, w*52+52); recurrent weights in registers.
// Per step: partial dots from SMEM-staged h -> warp0 reduce+activations+publish
// (into buffer (t+1)&1: one full step of slack vs laggard readers),
// warp1 prefetches next input contribution, warp2 polls all ready flags.
__global__ void __launch_bounds__(NT, 1) lstm_rec_kernel(
    const float* __restrict__ w_hh,   // [4112][1028]
    const float* __restrict__ w_ih0,  // [4112] (layer 0 only)
    const float* __restrict__ b0,     // b_ih [4112]
    const float* __restrict__ b1,     // b_hh [4112]
    const float* __restrict__ xin,    // layer0: x[T]; layer1: g_ihc [T][4112]
    float* __restrict__ hout,         // layer0: g_h1 (stride KPAD); layer1: g_h2 (stride HDIM)
    int hstride, int layer)
{
    __shared__ float hs[HB];               // staged h for current step
    __shared__ float partial_s[NW * 32];
    __shared__ float xc_s[2][32];          // double-buffered input contribution

    const int tid = threadIdx.x;
    const int w   = tid >> 5;
    const int l   = tid & 31;
    const int s   = blockIdx.x;

    const int uu = l & 7;
    const int g  = l >> 3;
    const int u  = s * UPER + uu;
    const bool rowvalid = (u < HDIM);
    const int grow = g * HDIM + u;
    const int c0 = w * CPW;

    // --- one-time: recurrent weights into registers ---
    float wreg[CPW];
    #pragma unroll
    for (int j = 0; j < CPW; ++j) {
        int c = c0 + j;
        wreg[j] = (rowvalid && c < HDIM) ? w_hh[(long long)grow * HDIM + c] : 0.f;
    }
    float wih = 0.f, bsum = 0.f;
    if (rowvalid) {
        bsum = b0[grow] + b1[grow];
        if (layer == 0) wih = w_ih0[grow];
    }

    // --- init smem: h0 = 0, xc for t=0 ---
    for (int i = tid; i < HB; i += NT) hs[i] = 0.f;
    if (w == 1) {
        float v = 0.f;
        if (rowvalid)
            v = (layer == 0) ? fmaf(__ldg(&xin[0]), wih, bsum)
                             : __ldg(&xin[grow]) + bsum;
        xc_s[0][l] = v;
    }
    __syncthreads();

    const int rep = s & (RREP - 1);
    float creg = 0.f;   // cell state (warp 0, lanes < 8)

    for (int t = 0; t < T_STEPS; ++t) {
        // --- all warps: partial dot over own column chunk (SMEM broadcast) ---
        float a0 = 0.f, a1 = 0.f;
        #pragma unroll
        for (int j4 = 0; j4 < CPW / 4; ++j4) {
            float4 hv = *reinterpret_cast<const float4*>(&hs[c0 + 4 * j4]);
            a0 = fmaf(wreg[4 * j4 + 0], hv.x, a0);
            a1 = fmaf(wreg[4 * j4 + 1], hv.y, a1);
            a0 = fmaf(wreg[4 * j4 + 2], hv.z, a0);
            a1 = fmaf(wreg[4 * j4 + 3], hv.w, a1);
        }
        partial_s[(w << 5) + l] = a0 + a1;
        __syncthreads();

        if (w == 0) {
            // --- reduce across warps ---
            float sv = xc_s[t & 1][l];
            float s0 = 0.f, s1 = 0.f, s2 = 0.f, s3 = 0.f;
            #pragma unroll
            for (int ww = 0; ww < NW; ww += 4) {
                s0 += partial_s[((ww + 0) << 5) + l];
                s1 += partial_s[((ww + 1) << 5) + l];
                s2 += partial_s[((ww + 2) << 5) + l];
                s3 += partial_s[((ww + 3) << 5) + l];
            }
            sv += (s0 + s1) + (s2 + s3);
            // gather the 4 gates of unit (l&7): lanes uu, uu+8, uu+16, uu+24
            float iv = __shfl_sync(0xffffffffu, sv, uu + 0);
            float fv = __shfl_sync(0xffffffffu, sv, uu + 8);
            float gv = __shfl_sync(0xffffffffu, sv, uu + 16);
            float ov = __shfl_sync(0xffffffffu, sv, uu + 24);
            if (l < 8) {
                int uo = s * UPER + l;
                if (uo < HDIM) {
                    iv = sigm(iv);
                    fv = sigm(fv);
                    gv = tanhf(gv);
                    ov = sigm(ov);
                    float c2 = fmaf(fv, creg, iv * gv);
                    creg = c2;
                    float hh = ov * tanhf(c2);
                    float* dst = &g_hrep[(t + 1) & 1][0];
                    #pragma unroll
                    for (int r = 0; r < RREP; ++r)
                        __stcg(&dst[r * RSTRIDE + uo], hh);
                    hout[(long long)t * hstride + uo] = hh;
                }
            }
            __syncwarp();
            if (l == 0) {
                __threadfence();   // order h stores before flag (CG grid-sync pattern)
                unsigned tv = (unsigned)(t + 1);
                asm volatile("st.global.release.gpu.u32 [%0], %1;"
                             :: "l"(&g_ready[s]), "r"(tv) : "memory");
            }
        } else if (w == 1) {
            // --- prefetch input contribution for t+1 ---
            if (t + 1 < T_STEPS) {
                float v = 0.f;
                if (rowvalid)
                    v = (layer == 0) ? fmaf(__ldg(&xin[t + 1]), wih, bsum)
                                     : __ldg(&xin[(long long)(t + 1) * G4 + grow]) + bsum;
                xc_s[(t + 1) & 1][l] = v;
            }
        } else if (w == 2) {
            // --- poll all CTA flags (distributed barrier) ---
            unsigned tgt = (unsigned)(t + 1);
            bool done = false;
            while (!done) {
                unsigned ok = 1u;
                #pragma unroll
                for (int k = 0; k < 5; ++k) {
                    int idx = l + 32 * k;
                    if (idx < NCTA) {
                        unsigned f;
                        asm volatile("ld.acquire.gpu.global.u32 %0, [%1];"
                                     : "=r"(f) : "l"(&g_ready[idx]) : "memory");
                        ok &= (f >= tgt) ? 1u : 0u;
                    }
                }
                done = (__all_sync(0xffffffffu, (int)ok) != 0);
            }
        }
        __syncthreads();

        // --- stage h_{t+1} from buffer (t+1)&1: coalesced L2 read -> SMEM ---
        // (each warp stages exactly the chunk it will read; __syncwarp suffices)
        if (l < CPW / 4) {
            float4 hv = __ldcg(reinterpret_cast<const float4*>(
                               &g_hrep[(t + 1) & 1][rep * RSTRIDE + c0 + 4 * l]));
            *reinterpret_cast<float4*>(&hs[c0 + 4 * l]) = hv;
        }
        __syncwarp();
    }
}

// ---------------- fp32 SGEMM: g_ihc[T][4112] = g_h1[T][KPAD] * g_wpad[4112][KPAD]^T ----------------
__global__ void __launch_bounds__(256, 2) sgemm_kernel(float* __restrict__ C)
{
    __shared__ float As[8][128];
    __shared__ float Bs[8][128];

    const int tid = threadIdx.x;
    const int m0 = blockIdx.y * 128;
    const int n0 = blockIdx.x * 128;

    const int lr = tid >> 1;
    const int lc = (tid & 1) * 4;
    const float* Ap = g_h1 + (long long)(m0 + lr) * KPAD + lc;
    const int brow = n0 + lr;
    const float* Bp = g_wpad + (long long)brow * KPAD + lc;
    const bool bvalid = (brow < G4);

    const int tx = tid & 15;
    const int ty = tid >> 4;

    float acc[8][8];
    #pragma unroll
    for (int i = 0; i < 8; ++i)
        #pragma unroll
        for (int j = 0; j < 8; ++j) acc[i][j] = 0.f;

    for (int k0 = 0; k0 < KPAD; k0 += 8) {
        float4 av = *reinterpret_cast<const float4*>(Ap + k0);
        float4 bv = bvalid ? *reinterpret_cast<const float4*>(Bp + k0)
                           : make_float4(0.f, 0.f, 0.f, 0.f);
        __syncthreads();
        As[lc + 0][lr] = av.x; As[lc + 1][lr] = av.y;
        As[lc + 2][lr] = av.z; As[lc + 3][lr] = av.w;
        Bs[lc + 0][lr] = bv.x; Bs[lc + 1][lr] = bv.y;
        Bs[lc + 2][lr] = bv.z; Bs[lc + 3][lr] = bv.w;
        __syncthreads();
        #pragma unroll
        for (int kk = 0; kk < 8; ++kk) {
            float ra[8], rb[8];
            #pragma unroll
            for (int i = 0; i < 8; ++i) ra[i] = As[kk][ty * 8 + i];
            #pragma unroll
            for (int j = 0; j < 8; ++j) rb[j] = Bs[kk][tx * 8 + j];
            #pragma unroll
            for (int i = 0; i < 8; ++i)
                #pragma unroll
                for (int j = 0; j < 8; ++j)
                    acc[i][j] = fmaf(ra[i], rb[j], acc[i][j]);
        }
    }

    #pragma unroll
    for (int i = 0; i < 8; ++i) {
        int m = m0 + ty * 8 + i;
        #pragma unroll
        for (int j = 0; j < 8; ++j) {
            int n = n0 + tx * 8 + j;
            if (n < G4) C[(long long)m * G4 + n] = acc[i][j];
        }
    }
}

// ---------------- final linear: out[t] = h2[t] . lin_w + lin_b ----------------
__global__ void outdot_kernel(const float* __restrict__ lw,
                              const float* __restrict__ lb,
                              float* __restrict__ out)
{
    const int w = threadIdx.x >> 5;
    const int l = threadIdx.x & 31;
    const int t = blockIdx.x * 4 + w;
    if (t >= T_STEPS) return;
    const float* h = g_h2 + (long long)t * HDIM;
    float acc = 0.f;
    for (int u = l; u < HDIM; u += 32) acc = fmaf(h[u], lw[u], acc);
    #pragma unroll
    for (int o = 16; o; o >>= 1) acc += __shfl_down_sync(0xffffffffu, acc, o);
    if (l == 0) out[t] = acc + lb[0];
}

// ---------------- launch ----------------
extern "C" void kernel_launch(void* const* d_in, const int* in_sizes, int n_in,
                              void* d_out, int out_size)
{
    const float* x     = (const float*)d_in[0];
    const float* w_ih0 = (const float*)d_in[1];
    const float* w_hh0 = (const float*)d_in[2];
    const float* b_ih0 = (const float*)d_in[3];
    const float* b_hh0 = (const float*)d_in[4];
    const float* w_ih1 = (const float*)d_in[5];
    const float* w_hh1 = (const float*)d_in[6];
    const float* b_ih1 = (const float*)d_in[7];
    const float* b_hh1 = (const float*)d_in[8];
    const float* lin_w = (const float*)d_in[9];
    const float* lin_b = (const float*)d_in[10];
    float* out = (float*)d_out;

    void *p_h1, *p_ihc, *p_hrep, *p_ready, *p_h2;
    cudaGetSymbolAddress(&p_h1,    g_h1);
    cudaGetSymbolAddress(&p_ihc,   g_ihc);
    cudaGetSymbolAddress(&p_hrep,  g_hrep);
    cudaGetSymbolAddress(&p_ready, g_ready);
    cudaGetSymbolAddress(&p_h2,    g_h2);

    // zero: h1 (for K-padding), both h replica buffers, flags
    cudaMemsetAsync(p_h1,    0, sizeof(float) * (size_t)T_STEPS * KPAD);
    cudaMemsetAsync(p_hrep,  0, sizeof(float) * 2 * RREP * RSTRIDE);
    cudaMemsetAsync(p_ready, 0, sizeof(unsigned) * NCTA);

    // pad w_ih1 for the GEMM
    pad_w_kernel<<<G4, 256>>>(w_ih1);

    // layer-0 recurrence
    lstm_rec_kernel<<<NCTA, NT>>>(w_hh0, w_ih0, b_ih0, b_hh0, x,
                                  (float*)p_h1, KPAD, 0);

    // ihc = h1 @ w_ih1^T (biases added inside recurrence kernel)
    dim3 gB(33, 128);
    sgemm_kernel<<<gB, 256>>>((float*)p_ihc);

    // reset flags + h replica buffers for layer 1
    cudaMemsetAsync(p_hrep,  0, sizeof(float) * 2 * RREP * RSTRIDE);
    cudaMemsetAsync(p_ready, 0, sizeof(unsigned) * NCTA);

    // layer-1 recurrence
    lstm_rec_kernel<<<NCTA, NT>>>(w_hh1, nullptr, b_ih1, b_hh1,
                                  (const float*)p_ihc, (float*)p_h2, HDIM, 1);

    // final projection
    outdot_kernel<<<(T_STEPS + 3) / 4, 128>>>(lin_w, lin_b, out);
}